// round 7
// baseline (speedup 1.0000x reference)
#include <cuda_runtime.h>
#include <cuda_fp16.h>
#include <cstddef>

#define NN 100000
#define INC 128
#define HC 128
#define SLOT 64            // padded edge slots per node (P(deg>64) ~ 4e-13)
#define NEG 0.2f
#define PSCALE 0.015625f   // 1/64 uniform numerator scale, cancels in softmax

typedef unsigned long long ull;

// ------------------------- scratch (device globals) -------------------------
__device__ __half g_hp[(size_t)NN * HC];        // h packed [node][col(32)][head(4)]
__device__ float  g_asrc[NN * 4];
__device__ float  g_adst[NN * 4];
__device__ int    g_counts[NN];
__device__ int    g_esrc[(size_t)NN * SLOT];    // src index per slot
__device__ uint2  g_epv[(size_t)NN * SLOT];     // numerators p01,p23 fp16x2 per slot

__device__ __forceinline__ float lrelu(float s) { return s > 0.0f ? s : NEG * s; }

__device__ __forceinline__ void mma16816(
    float& c0, float& c1, float& c2, float& c3,
    unsigned a0, unsigned a1, unsigned a2, unsigned a3,
    unsigned b0, unsigned b1)
{
    asm volatile(
        "mma.sync.aligned.m16n8k16.row.col.f32.f16.f16.f32 "
        "{%0,%1,%2,%3}, {%4,%5,%6,%7}, {%8,%9}, {%0,%1,%2,%3};"
        : "+f"(c0), "+f"(c1), "+f"(c2), "+f"(c3)
        : "r"(a0), "r"(a1), "r"(a2), "r"(a3), "r"(b0), "r"(b1));
}

// ---------------------------------------------------------------------------
// Kernel 1: tensor-core GEMM h = x @ W (fp16 in, fp32 acc) + fused attention
// dots + packed fp16 h store. Also zeroes the degree counters (fold of the
// old k_zero launch: gemm grid has >= NN threads).
// ---------------------------------------------------------------------------
#define XP 72

__global__ void __launch_bounds__(256) k_gemm(
    const float* __restrict__ x, const float* __restrict__ W,
    const float* __restrict__ att_src, const float* __restrict__ att_dst)
{
    __shared__ __align__(16) __half sbuf[2][128 * XP];
    __shared__ float asmem[128], admem[128];
    __half* xs = sbuf[0];
    __half* ws = sbuf[1];

    const int t = threadIdx.x;
    const int blk = blockIdx.x;
    const int w = t >> 5;
    const int lane = t & 31;
    const int quad = lane >> 2;
    const int tq = lane & 3;

    // fold: zero degree counters
    {
        int gidz = blk * 256 + t;
        if (gidz < NN) g_counts[gidz] = 0;
    }

    if (t < 128) { asmem[t] = att_src[t]; admem[t] = att_dst[t]; }

    float acc[16][4];
#pragma unroll
    for (int nt = 0; nt < 16; nt++)
#pragma unroll
        for (int j = 0; j < 4; j++) acc[nt][j] = 0.0f;

    for (int kc = 0; kc < 2; kc++) {
#pragma unroll
        for (int i = 0; i < 8; i++) {
            int f = t + 256 * i;
            int r = f >> 4;
            int q = f & 15;
            int row = blk * 128 + r;
            if (row >= NN) row = NN - 1;
            float4 v = *reinterpret_cast<const float4*>(
                x + (size_t)row * INC + kc * 64 + q * 4);
            __half2 h01 = __floats2half2_rn(v.x, v.y);
            __half2 h23 = __floats2half2_rn(v.z, v.w);
            uint2 pk = make_uint2(*reinterpret_cast<unsigned*>(&h01),
                                  *reinterpret_cast<unsigned*>(&h23));
            *reinterpret_cast<uint2*>(&xs[r * XP + q * 4]) = pk;
        }
#pragma unroll
        for (int i = 0; i < 8; i++) {
            int f = t + 256 * i;
            int k = f >> 5;
            int q = f & 31;
            int n0 = q * 4;
            float4 v = *reinterpret_cast<const float4*>(
                W + (size_t)(kc * 64 + k) * HC + n0);
            ws[(n0 + 0) * XP + k] = __float2half_rn(v.x);
            ws[(n0 + 1) * XP + k] = __float2half_rn(v.y);
            ws[(n0 + 2) * XP + k] = __float2half_rn(v.z);
            ws[(n0 + 3) * XP + k] = __float2half_rn(v.w);
        }
        __syncthreads();

#pragma unroll
        for (int ks = 0; ks < 4; ks++) {
            const int kk = ks * 16 + tq * 2;
            const int rw = 16 * w;
            unsigned a0 = *reinterpret_cast<const unsigned*>(&xs[(rw + quad) * XP + kk]);
            unsigned a1 = *reinterpret_cast<const unsigned*>(&xs[(rw + quad + 8) * XP + kk]);
            unsigned a2 = *reinterpret_cast<const unsigned*>(&xs[(rw + quad) * XP + kk + 8]);
            unsigned a3 = *reinterpret_cast<const unsigned*>(&xs[(rw + quad + 8) * XP + kk + 8]);
#pragma unroll
            for (int nt = 0; nt < 16; nt++) {
                unsigned b0 = *reinterpret_cast<const unsigned*>(&ws[(nt * 8 + quad) * XP + kk]);
                unsigned b1 = *reinterpret_cast<const unsigned*>(&ws[(nt * 8 + quad) * XP + kk + 8]);
                mma16816(acc[nt][0], acc[nt][1], acc[nt][2], acc[nt][3],
                         a0, a1, a2, a3, b0, b1);
            }
        }
        __syncthreads();
    }

    float ps0[4] = {0, 0, 0, 0}, pd0[4] = {0, 0, 0, 0};
    float ps1[4] = {0, 0, 0, 0}, pd1[4] = {0, 0, 0, 0};
#pragma unroll
    for (int nt = 0; nt < 16; nt++) {
        const int h = nt >> 2;
        const int c = nt * 8 + tq * 2;
        const float As0 = asmem[c], As1 = asmem[c + 1];
        const float Ad0 = admem[c], Ad1 = admem[c + 1];
        ps0[h] += acc[nt][0] * As0 + acc[nt][1] * As1;
        pd0[h] += acc[nt][0] * Ad0 + acc[nt][1] * Ad1;
        ps1[h] += acc[nt][2] * As0 + acc[nt][3] * As1;
        pd1[h] += acc[nt][2] * Ad0 + acc[nt][3] * Ad1;
    }
#pragma unroll
    for (int o = 1; o <= 2; o <<= 1) {
#pragma unroll
        for (int h = 0; h < 4; h++) {
            ps0[h] += __shfl_xor_sync(0xffffffffu, ps0[h], o);
            pd0[h] += __shfl_xor_sync(0xffffffffu, pd0[h], o);
            ps1[h] += __shfl_xor_sync(0xffffffffu, ps1[h], o);
            pd1[h] += __shfl_xor_sync(0xffffffffu, pd1[h], o);
        }
    }
    const int r0 = blk * 128 + 16 * w + quad;
    const int r1 = r0 + 8;
    if (tq == 0) {
        if (r0 < NN) {
#pragma unroll
            for (int h = 0; h < 4; h++) {
                g_asrc[r0 * 4 + h] = ps0[h];
                g_adst[r0 * 4 + h] = pd0[h];
            }
        }
        if (r1 < NN) {
#pragma unroll
            for (int h = 0; h < 4; h++) {
                g_asrc[r1 * 4 + h] = ps1[h];
                g_adst[r1 * 4 + h] = pd1[h];
            }
        }
    }

    __half* hs = sbuf[0];
    const int lr0 = 16 * w + quad;
#pragma unroll
    for (int nt = 0; nt < 16; nt++) {
        const int c = nt * 8 + tq * 2;
        const int p0 = (c & 31) * 4 + (c >> 5);
        const int p1 = ((c + 1) & 31) * 4 + ((c + 1) >> 5);
        hs[lr0 * 128 + p0] = __float2half_rn(acc[nt][0]);
        hs[lr0 * 128 + p1] = __float2half_rn(acc[nt][1]);
        hs[(lr0 + 8) * 128 + p0] = __float2half_rn(acc[nt][2]);
        hs[(lr0 + 8) * 128 + p1] = __float2half_rn(acc[nt][3]);
    }
    __syncthreads();

#pragma unroll
    for (int i = 0; i < 8; i++) {
        int f = t + 256 * i;
        int lr = f >> 4;
        int q = f & 15;
        int row = blk * 128 + lr;
        if (row < NN) {
            uint4 v = reinterpret_cast<const uint4*>(&hs[lr * 128])[q];
            reinterpret_cast<uint4*>(g_hp + (size_t)row * HC)[q] = v;
        }
    }
}

// ---------------------------------------------------------------------------
// Kernel 2: fused histogram + numerator exp + split record write.
// ---------------------------------------------------------------------------
__global__ void k_scatter(const int* __restrict__ ei, int E) {
    int e = blockIdx.x * blockDim.x + threadIdx.x;
    if (e >= E) return;
    int src = ei[e];
    int dst = ei[E + e];
    int epos = atomicAdd(&g_counts[dst], 1);
    if (epos >= SLOT) return;   // astronomically unlikely; drop to stay safe
    const float4 as = *reinterpret_cast<const float4*>(g_asrc + (size_t)src * 4);
    const float4 ad = *reinterpret_cast<const float4*>(g_adst + (size_t)dst * 4);
    float p0 = __expf(lrelu(as.x + ad.x)) * PSCALE;
    float p1 = __expf(lrelu(as.y + ad.y)) * PSCALE;
    float p2 = __expf(lrelu(as.z + ad.z)) * PSCALE;
    float p3 = __expf(lrelu(as.w + ad.w)) * PSCALE;
    __half2 h01 = __floats2half2_rn(p0, p1);
    __half2 h23 = __floats2half2_rn(p2, p3);
    size_t pos = (size_t)dst * SLOT + epos;
    g_esrc[pos] = src;
    g_epv[pos] = make_uint2(*reinterpret_cast<unsigned*>(&h01),
                            *reinterpret_cast<unsigned*>(&h23));
}

// ---------------------------------------------------------------------------
// Kernel 3: warp-per-dst aggregate. Block = 64 (2 warps) for fine-grained
// completion + higher occupancy. Uniform record loads, 8-deep gather MLP,
// half2 packed FMA with fp32 flush every 4 edges.
// ---------------------------------------------------------------------------
__global__ void __launch_bounds__(64) k_agg(float* __restrict__ out,
                                            const float* __restrict__ bias) {
    const int gid = blockIdx.x * 64 + threadIdx.x;
    const int node = gid >> 5;
    const int lane = gid & 31;
    if (node >= NN) return;

    const uint2* hp = reinterpret_cast<const uint2*>(g_hp);

    // self-loop in fp32 (same 1/64 scale — cancels)
    const float4 as = *reinterpret_cast<const float4*>(g_asrc + (size_t)node * 4);
    const float4 ad = *reinterpret_cast<const float4*>(g_adst + (size_t)node * 4);
    float p0 = __expf(lrelu(as.x + ad.x)) * PSCALE;
    float p1 = __expf(lrelu(as.y + ad.y)) * PSCALE;
    float p2 = __expf(lrelu(as.z + ad.z)) * PSCALE;
    float p3 = __expf(lrelu(as.w + ad.w)) * PSCALE;
    uint2 hv = hp[(size_t)node * 32 + lane];
    float2 f01 = __half22float2(*reinterpret_cast<__half2*>(&hv.x));
    float2 f23 = __half22float2(*reinterpret_cast<__half2*>(&hv.y));
    float A0 = p0 * f01.x, A1 = p1 * f01.y;
    float A2 = p2 * f23.x, A3 = p3 * f23.y;
    float D0 = p0, D1 = p1, D2 = p2, D3 = p3;

    const int*  es = g_esrc + (size_t)node * SLOT;
    const uint2* ep = g_epv + (size_t)node * SLOT;
    int deg = g_counts[node];
    if (deg > SLOT) deg = SLOT;
    const __half2 z2 = __float2half2_rn(0.0f);

#define EDGEH(qq, hh)                                                         \
    {                                                                         \
        __half2 pp01 = *reinterpret_cast<const __half2*>(&(qq).x);            \
        __half2 pp23 = *reinterpret_cast<const __half2*>(&(qq).y);            \
        __half2 gg01 = *reinterpret_cast<const __half2*>(&(hh).x);            \
        __half2 gg23 = *reinterpret_cast<const __half2*>(&(hh).y);            \
        acc01 = __hfma2(pp01, gg01, acc01);                                   \
        acc23 = __hfma2(pp23, gg23, acc23);                                   \
        den01 = __hadd2(den01, pp01);                                         \
        den23 = __hadd2(den23, pp23);                                         \
    }
#define FLUSH                                                                 \
    {                                                                         \
        float2 t;                                                             \
        t = __half22float2(acc01); A0 += t.x; A1 += t.y;                      \
        t = __half22float2(acc23); A2 += t.x; A3 += t.y;                      \
        t = __half22float2(den01); D0 += t.x; D1 += t.y;                      \
        t = __half22float2(den23); D2 += t.x; D3 += t.y;                      \
        acc01 = z2; acc23 = z2; den01 = z2; den23 = z2;                       \
    }

    int j = 0;
    for (; j + 8 <= deg; j += 8) {
        int s0 = es[j],     s1 = es[j + 1], s2 = es[j + 2], s3 = es[j + 3];
        int s4 = es[j + 4], s5 = es[j + 5], s6 = es[j + 6], s7 = es[j + 7];
        uint2 h0 = hp[(size_t)s0 * 32 + lane];
        uint2 h1 = hp[(size_t)s1 * 32 + lane];
        uint2 h2 = hp[(size_t)s2 * 32 + lane];
        uint2 h3 = hp[(size_t)s3 * 32 + lane];
        uint2 h4 = hp[(size_t)s4 * 32 + lane];
        uint2 h5 = hp[(size_t)s5 * 32 + lane];
        uint2 h6 = hp[(size_t)s6 * 32 + lane];
        uint2 h7 = hp[(size_t)s7 * 32 + lane];
        uint2 q0 = ep[j],     q1 = ep[j + 1], q2 = ep[j + 2], q3 = ep[j + 3];
        uint2 q4 = ep[j + 4], q5 = ep[j + 5], q6 = ep[j + 6], q7 = ep[j + 7];
        __half2 acc01 = z2, acc23 = z2, den01 = z2, den23 = z2;
        EDGEH(q0, h0) EDGEH(q1, h1) EDGEH(q2, h2) EDGEH(q3, h3)
        FLUSH
        EDGEH(q4, h4) EDGEH(q5, h5) EDGEH(q6, h6) EDGEH(q7, h7)
        FLUSH
    }
    for (; j + 4 <= deg; j += 4) {
        int s0 = es[j], s1 = es[j + 1], s2 = es[j + 2], s3 = es[j + 3];
        uint2 h0 = hp[(size_t)s0 * 32 + lane];
        uint2 h1 = hp[(size_t)s1 * 32 + lane];
        uint2 h2 = hp[(size_t)s2 * 32 + lane];
        uint2 h3 = hp[(size_t)s3 * 32 + lane];
        uint2 q0 = ep[j], q1 = ep[j + 1], q2 = ep[j + 2], q3 = ep[j + 3];
        __half2 acc01 = z2, acc23 = z2, den01 = z2, den23 = z2;
        EDGEH(q0, h0) EDGEH(q1, h1) EDGEH(q2, h2) EDGEH(q3, h3)
        FLUSH
    }
    {
        __half2 acc01 = z2, acc23 = z2, den01 = z2, den23 = z2;
        for (; j < deg; j++) {
            int s0 = es[j];
            uint2 h0 = hp[(size_t)s0 * 32 + lane];
            uint2 q0 = ep[j];
            EDGEH(q0, h0)
        }
        FLUSH
    }
#undef EDGEH
#undef FLUSH

    float v = 0.25f * (A0 / (D0 + 1e-16f) + A1 / (D1 + 1e-16f)
                     + A2 / (D2 + 1e-16f) + A3 / (D3 + 1e-16f))
            + bias[lane];
    out[(size_t)node * 32 + lane] = v > 0.0f ? v : 0.0f;
}

// ---------------------------------------------------------------------------
extern "C" void kernel_launch(void* const* d_in, const int* in_sizes, int n_in,
                              void* d_out, int out_size) {
    const float* x       = (const float*)d_in[0];
    const int*   ei      = (const int*)  d_in[1];
    const float* W       = (const float*)d_in[2];
    const float* att_src = (const float*)d_in[3];
    const float* att_dst = (const float*)d_in[4];
    const float* bias    = (const float*)d_in[5];
    float*       out     = (float*)d_out;

    const int E = in_sizes[1] / 2;

    k_gemm<<<(NN + 127) / 128, 256>>>(x, W, att_src, att_dst);
    k_scatter<<<(E + 255) / 256, 256>>>(ei, E);
    k_agg<<<(NN * 2 + 1) , 64>>>(out, bias);
}

// round 8
// speedup vs baseline: 1.5456x; 1.5456x over previous
#include <cuda_runtime.h>
#include <cuda_fp16.h>
#include <cstddef>
#include <cstdint>

#define NN 100000
#define INC 128
#define HC 128
#define SLOT 64            // padded edge slots per node (P(deg>64) ~ 4e-13)
#define NEG 0.2f
#define PSCALE 0.015625f   // 1/64 uniform numerator scale, cancels in softmax

typedef unsigned long long ull;

// ------------------------- scratch (device globals) -------------------------
__device__ __half g_hp[(size_t)NN * HC];        // h packed [node][col(32)][head(4)]
__device__ float  g_asrc[NN * 4];
__device__ float  g_adst[NN * 4];
__device__ int    g_counts[NN];
__device__ int4   g_edge[(size_t)NN * SLOT];    // {src, p01 fp16x2, p23 fp16x2, 0}

__device__ __forceinline__ float lrelu(float s) { return s > 0.0f ? s : NEG * s; }

__device__ __forceinline__ void mma16816(
    float& c0, float& c1, float& c2, float& c3,
    unsigned a0, unsigned a1, unsigned a2, unsigned a3,
    unsigned b0, unsigned b1)
{
    asm volatile(
        "mma.sync.aligned.m16n8k16.row.col.f32.f16.f16.f32 "
        "{%0,%1,%2,%3}, {%4,%5,%6,%7}, {%8,%9}, {%0,%1,%2,%3};"
        : "+f"(c0), "+f"(c1), "+f"(c2), "+f"(c3)
        : "r"(a0), "r"(a1), "r"(a2), "r"(a3), "r"(b0), "r"(b1));
}

__device__ __forceinline__ void ldsm_x4(
    unsigned& r0, unsigned& r1, unsigned& r2, unsigned& r3, uint32_t addr)
{
    asm volatile("ldmatrix.sync.aligned.m8n8.x4.shared.b16 {%0,%1,%2,%3}, [%4];"
                 : "=r"(r0), "=r"(r1), "=r"(r2), "=r"(r3) : "r"(addr));
}

__device__ __forceinline__ void ldsm_x4t(
    unsigned& r0, unsigned& r1, unsigned& r2, unsigned& r3, uint32_t addr)
{
    asm volatile("ldmatrix.sync.aligned.m8n8.x4.trans.shared.b16 {%0,%1,%2,%3}, [%4];"
                 : "=r"(r0), "=r"(r1), "=r"(r2), "=r"(r3) : "r"(addr));
}

// ---------------------------------------------------------------------------
// Kernel 1: tensor-core GEMM h = x @ W + fused attention dots + packed fp16 h.
// ldmatrix-based fragments: A from x tile [r][k] (pitch 72 halves, non-trans),
// B from W tile [k][n] row-major (pitch 136 halves, .trans). Both pitches
// give 8-row bank rotation 4i mod 32 -> conflict-free LDSM; staging stores
// are conflict-free uint2. Also zeroes degree counters.
// ---------------------------------------------------------------------------
#define XP 72      // x tile pitch (halves)
#define WPAD 136   // W tile pitch (halves)

__global__ void __launch_bounds__(256) k_gemm(
    const float* __restrict__ x, const float* __restrict__ W,
    const float* __restrict__ att_src, const float* __restrict__ att_dst)
{
    __shared__ __align__(16) __half pool[128 * XP + 64 * WPAD]; // 35.8 KB
    __shared__ float asmem[128], admem[128];
    __half* xs = pool;                 // [r][k] r<128, k<64
    __half* wk = pool + 128 * XP;      // [k][n] k<64,  n<128

    const int t = threadIdx.x;
    const int blk = blockIdx.x;
    const int w = t >> 5;
    const int lane = t & 31;
    const int quad = lane >> 2;
    const int tq = lane & 3;
    const int rw = 16 * w;

    // fold: zero degree counters
    {
        int gidz = blk * 256 + t;
        if (gidz < NN) g_counts[gidz] = 0;
    }
    if (t < 128) { asmem[t] = att_src[t]; admem[t] = att_dst[t]; }

    // per-lane ldmatrix base addresses
    const uint32_t xsBase = (uint32_t)__cvta_generic_to_shared(xs)
        + (uint32_t)(((rw + (lane & 15)) * XP + ((lane >> 4) << 3)) * 2);
    const uint32_t wkBase = (uint32_t)__cvta_generic_to_shared(wk)
        + (uint32_t)((((lane & 15)) * WPAD + ((lane >> 4) << 3)) * 2);

    float acc[16][4];
#pragma unroll
    for (int nt = 0; nt < 16; nt++)
#pragma unroll
        for (int j = 0; j < 4; j++) acc[nt][j] = 0.0f;

    for (int kc = 0; kc < 2; kc++) {
        // --- stage x tile: 128 rows x 64 k, fp16, [r][k] pitch XP ---
#pragma unroll
        for (int i = 0; i < 8; i++) {
            int f = t + 256 * i;          // 2048 float4
            int r = f >> 4;               // 16 float4 per row
            int q = f & 15;
            int row = blk * 128 + r;
            if (row >= NN) row = NN - 1;
            float4 v = *reinterpret_cast<const float4*>(
                x + (size_t)row * INC + kc * 64 + q * 4);
            __half2 h01 = __floats2half2_rn(v.x, v.y);
            __half2 h23 = __floats2half2_rn(v.z, v.w);
            uint2 pk = make_uint2(*reinterpret_cast<unsigned*>(&h01),
                                  *reinterpret_cast<unsigned*>(&h23));
            *reinterpret_cast<uint2*>(&xs[r * XP + q * 4]) = pk;
        }
        // --- stage W tile row-major [k][n]: 64 k-rows x 128 n, conflict-free ---
#pragma unroll
        for (int i = 0; i < 8; i++) {
            int f = t + 256 * i;          // 2048 float4
            int k = f >> 5;               // 32 float4 per k-row
            int q = f & 31;
            float4 v = *reinterpret_cast<const float4*>(
                W + (size_t)(kc * 64 + k) * HC + q * 4);
            __half2 h01 = __floats2half2_rn(v.x, v.y);
            __half2 h23 = __floats2half2_rn(v.z, v.w);
            uint2 pk = make_uint2(*reinterpret_cast<unsigned*>(&h01),
                                  *reinterpret_cast<unsigned*>(&h23));
            *reinterpret_cast<uint2*>(&wk[k * WPAD + q * 4]) = pk;
        }
        __syncthreads();

#pragma unroll
        for (int ks = 0; ks < 4; ks++) {
            unsigned a0, a1, a2, a3;
            ldsm_x4(a0, a1, a2, a3, xsBase + ks * 32);            // +16 halves
            const uint32_t bks = wkBase + (uint32_t)(ks * 16 * WPAD * 2);
#pragma unroll
            for (int nt2 = 0; nt2 < 8; nt2++) {
                unsigned b0, b1, b2, b3;
                ldsm_x4t(b0, b1, b2, b3, bks + nt2 * 32);         // +16 halves (n)
                mma16816(acc[2 * nt2][0], acc[2 * nt2][1],
                         acc[2 * nt2][2], acc[2 * nt2][3],
                         a0, a1, a2, a3, b0, b1);
                mma16816(acc[2 * nt2 + 1][0], acc[2 * nt2 + 1][1],
                         acc[2 * nt2 + 1][2], acc[2 * nt2 + 1][3],
                         a0, a1, a2, a3, b2, b3);
            }
        }
        __syncthreads();
    }

    // --- fused attention dots ---
    float ps0[4] = {0, 0, 0, 0}, pd0[4] = {0, 0, 0, 0};
    float ps1[4] = {0, 0, 0, 0}, pd1[4] = {0, 0, 0, 0};
#pragma unroll
    for (int nt = 0; nt < 16; nt++) {
        const int h = nt >> 2;
        const int c = nt * 8 + tq * 2;
        const float As0 = asmem[c], As1 = asmem[c + 1];
        const float Ad0 = admem[c], Ad1 = admem[c + 1];
        ps0[h] += acc[nt][0] * As0 + acc[nt][1] * As1;
        pd0[h] += acc[nt][0] * Ad0 + acc[nt][1] * Ad1;
        ps1[h] += acc[nt][2] * As0 + acc[nt][3] * As1;
        pd1[h] += acc[nt][2] * Ad0 + acc[nt][3] * Ad1;
    }
#pragma unroll
    for (int o = 1; o <= 2; o <<= 1) {
#pragma unroll
        for (int h = 0; h < 4; h++) {
            ps0[h] += __shfl_xor_sync(0xffffffffu, ps0[h], o);
            pd0[h] += __shfl_xor_sync(0xffffffffu, pd0[h], o);
            ps1[h] += __shfl_xor_sync(0xffffffffu, ps1[h], o);
            pd1[h] += __shfl_xor_sync(0xffffffffu, pd1[h], o);
        }
    }
    const int r0 = blk * 128 + rw + quad;
    const int r1 = r0 + 8;
    if (tq == 0) {
        if (r0 < NN) {
#pragma unroll
            for (int h = 0; h < 4; h++) {
                g_asrc[r0 * 4 + h] = ps0[h];
                g_adst[r0 * 4 + h] = pd0[h];
            }
        }
        if (r1 < NN) {
#pragma unroll
            for (int h = 0; h < 4; h++) {
                g_asrc[r1 * 4 + h] = ps1[h];
                g_adst[r1 * 4 + h] = pd1[h];
            }
        }
    }

    // --- stage h into smem packed [row][(c&31)*4 + (c>>5)], then copy out ---
    __half* hs = pool;   // 128*128 halves = 32 KB <= pool
    const int lr0 = rw + quad;
#pragma unroll
    for (int nt = 0; nt < 16; nt++) {
        const int c = nt * 8 + tq * 2;
        const int p0 = (c & 31) * 4 + (c >> 5);
        const int p1 = ((c + 1) & 31) * 4 + ((c + 1) >> 5);
        hs[lr0 * 128 + p0] = __float2half_rn(acc[nt][0]);
        hs[lr0 * 128 + p1] = __float2half_rn(acc[nt][1]);
        hs[(lr0 + 8) * 128 + p0] = __float2half_rn(acc[nt][2]);
        hs[(lr0 + 8) * 128 + p1] = __float2half_rn(acc[nt][3]);
    }
    __syncthreads();

#pragma unroll
    for (int i = 0; i < 8; i++) {
        int f = t + 256 * i;
        int lr = f >> 4;
        int q = f & 15;
        int row = blk * 128 + lr;
        if (row < NN) {
            uint4 v = reinterpret_cast<const uint4*>(&hs[lr * 128])[q];
            reinterpret_cast<uint4*>(g_hp + (size_t)row * HC)[q] = v;
        }
    }
}

// ---------------------------------------------------------------------------
// Kernel 2: fused histogram + numerator exp + AOS record write.
// ---------------------------------------------------------------------------
__global__ void k_scatter(const int* __restrict__ ei, int E) {
    int e = blockIdx.x * blockDim.x + threadIdx.x;
    if (e >= E) return;
    int src = ei[e];
    int dst = ei[E + e];
    int epos = atomicAdd(&g_counts[dst], 1);
    if (epos >= SLOT) return;   // astronomically unlikely; drop to stay safe
    const float4 as = *reinterpret_cast<const float4*>(g_asrc + (size_t)src * 4);
    const float4 ad = *reinterpret_cast<const float4*>(g_adst + (size_t)dst * 4);
    float p0 = __expf(lrelu(as.x + ad.x)) * PSCALE;
    float p1 = __expf(lrelu(as.y + ad.y)) * PSCALE;
    float p2 = __expf(lrelu(as.z + ad.z)) * PSCALE;
    float p3 = __expf(lrelu(as.w + ad.w)) * PSCALE;
    __half2 h01 = __floats2half2_rn(p0, p1);
    __half2 h23 = __floats2half2_rn(p2, p3);
    int4 rec;
    rec.x = src;
    rec.y = *reinterpret_cast<int*>(&h01);
    rec.z = *reinterpret_cast<int*>(&h23);
    rec.w = 0;
    g_edge[(size_t)dst * SLOT + epos] = rec;
}

// ---------------------------------------------------------------------------
// Kernel 3: warp-per-dst aggregate (R6 form: 256-thr blocks, AOS records,
// uniform LDG.128, 8-deep gather MLP, half2 math, fp32 flush every 4 edges).
// ---------------------------------------------------------------------------
__global__ void __launch_bounds__(256) k_agg(float* __restrict__ out,
                                             const float* __restrict__ bias) {
    const int gid = blockIdx.x * blockDim.x + threadIdx.x;
    const int node = gid >> 5;
    const int lane = gid & 31;
    if (node >= NN) return;

    const uint2* hp = reinterpret_cast<const uint2*>(g_hp);

    const float4 as = *reinterpret_cast<const float4*>(g_asrc + (size_t)node * 4);
    const float4 ad = *reinterpret_cast<const float4*>(g_adst + (size_t)node * 4);
    float p0 = __expf(lrelu(as.x + ad.x)) * PSCALE;
    float p1 = __expf(lrelu(as.y + ad.y)) * PSCALE;
    float p2 = __expf(lrelu(as.z + ad.z)) * PSCALE;
    float p3 = __expf(lrelu(as.w + ad.w)) * PSCALE;
    uint2 hv = hp[(size_t)node * 32 + lane];
    float2 f01 = __half22float2(*reinterpret_cast<__half2*>(&hv.x));
    float2 f23 = __half22float2(*reinterpret_cast<__half2*>(&hv.y));
    float A0 = p0 * f01.x, A1 = p1 * f01.y;
    float A2 = p2 * f23.x, A3 = p3 * f23.y;
    float D0 = p0, D1 = p1, D2 = p2, D3 = p3;

    const int4* ge = g_edge + (size_t)node * SLOT;
    int deg = g_counts[node];
    if (deg > SLOT) deg = SLOT;
    const __half2 z2 = __float2half2_rn(0.0f);

#define EDGEH(rec, hh)                                                        \
    {                                                                         \
        __half2 pp01 = *reinterpret_cast<const __half2*>(&(rec).y);           \
        __half2 pp23 = *reinterpret_cast<const __half2*>(&(rec).z);           \
        __half2 gg01 = *reinterpret_cast<const __half2*>(&(hh).x);            \
        __half2 gg23 = *reinterpret_cast<const __half2*>(&(hh).y);            \
        acc01 = __hfma2(pp01, gg01, acc01);                                   \
        acc23 = __hfma2(pp23, gg23, acc23);                                   \
        den01 = __hadd2(den01, pp01);                                         \
        den23 = __hadd2(den23, pp23);                                         \
    }
#define FLUSH                                                                 \
    {                                                                         \
        float2 t;                                                             \
        t = __half22float2(acc01); A0 += t.x; A1 += t.y;                      \
        t = __half22float2(acc23); A2 += t.x; A3 += t.y;                      \
        t = __half22float2(den01); D0 += t.x; D1 += t.y;                      \
        t = __half22float2(den23); D2 += t.x; D3 += t.y;                      \
        acc01 = z2; acc23 = z2; den01 = z2; den23 = z2;                       \
    }

    int j = 0;
    for (; j + 8 <= deg; j += 8) {
        int4 e0 = ge[j],     e1 = ge[j + 1], e2 = ge[j + 2], e3 = ge[j + 3];
        int4 e4 = ge[j + 4], e5 = ge[j + 5], e6 = ge[j + 6], e7 = ge[j + 7];
        uint2 h0 = hp[(size_t)e0.x * 32 + lane];
        uint2 h1 = hp[(size_t)e1.x * 32 + lane];
        uint2 h2 = hp[(size_t)e2.x * 32 + lane];
        uint2 h3 = hp[(size_t)e3.x * 32 + lane];
        uint2 h4 = hp[(size_t)e4.x * 32 + lane];
        uint2 h5 = hp[(size_t)e5.x * 32 + lane];
        uint2 h6 = hp[(size_t)e6.x * 32 + lane];
        uint2 h7 = hp[(size_t)e7.x * 32 + lane];
        __half2 acc01 = z2, acc23 = z2, den01 = z2, den23 = z2;
        EDGEH(e0, h0) EDGEH(e1, h1) EDGEH(e2, h2) EDGEH(e3, h3)
        FLUSH
        EDGEH(e4, h4) EDGEH(e5, h5) EDGEH(e6, h6) EDGEH(e7, h7)
        FLUSH
    }
    for (; j + 4 <= deg; j += 4) {
        int4 e0 = ge[j], e1 = ge[j + 1], e2 = ge[j + 2], e3 = ge[j + 3];
        uint2 h0 = hp[(size_t)e0.x * 32 + lane];
        uint2 h1 = hp[(size_t)e1.x * 32 + lane];
        uint2 h2 = hp[(size_t)e2.x * 32 + lane];
        uint2 h3 = hp[(size_t)e3.x * 32 + lane];
        __half2 acc01 = z2, acc23 = z2, den01 = z2, den23 = z2;
        EDGEH(e0, h0) EDGEH(e1, h1) EDGEH(e2, h2) EDGEH(e3, h3)
        FLUSH
    }
    {
        __half2 acc01 = z2, acc23 = z2, den01 = z2, den23 = z2;
        for (; j < deg; j++) {
            int4 e0 = ge[j];
            uint2 h0 = hp[(size_t)e0.x * 32 + lane];
            EDGEH(e0, h0)
        }
        FLUSH
    }
#undef EDGEH
#undef FLUSH

    float v = 0.25f * (A0 / (D0 + 1e-16f) + A1 / (D1 + 1e-16f)
                     + A2 / (D2 + 1e-16f) + A3 / (D3 + 1e-16f))
            + bias[lane];
    out[(size_t)node * 32 + lane] = v > 0.0f ? v : 0.0f;
}

// ---------------------------------------------------------------------------
extern "C" void kernel_launch(void* const* d_in, const int* in_sizes, int n_in,
                              void* d_out, int out_size) {
    const float* x       = (const float*)d_in[0];
    const int*   ei      = (const int*)  d_in[1];
    const float* W       = (const float*)d_in[2];
    const float* att_src = (const float*)d_in[3];
    const float* att_dst = (const float*)d_in[4];
    const float* bias    = (const float*)d_in[5];
    float*       out     = (float*)d_out;

    const int E = in_sizes[1] / 2;

    k_gemm<<<(NN + 127) / 128, 256>>>(x, W, att_src, att_dst);
    k_scatter<<<(E + 255) / 256, 256>>>(ei, E);
    k_agg<<<(NN * 32 + 255) / 256, 256>>>(out, bias);
}

// round 9
// speedup vs baseline: 1.6486x; 1.0667x over previous
#include <cuda_runtime.h>
#include <cuda_fp16.h>
#include <cstddef>
#include <cstdint>

#define NN 100000
#define INC 128
#define HC 128
#define SLOT 64            // padded edge slots per node (P(deg>64) ~ 4e-13)
#define NEG 0.2f
#define PSCALE 0.015625f   // 1/64 uniform numerator scale, cancels in softmax

typedef unsigned long long ull;

// ------------------------- scratch (device globals) -------------------------
__device__ __half g_hp[(size_t)NN * HC];        // h packed [node][col(32)][head(4)]
__device__ float  g_asrc[NN * 4];
__device__ float  g_adst[NN * 4];
__device__ int    g_counts[NN];
__device__ int4   g_edge[(size_t)NN * SLOT];    // {src, p01 fp16x2, p23 fp16x2, 0}

__device__ __forceinline__ float lrelu(float s) { return s > 0.0f ? s : NEG * s; }

__device__ __forceinline__ void mma16816(
    float& c0, float& c1, float& c2, float& c3,
    unsigned a0, unsigned a1, unsigned a2, unsigned a3,
    unsigned b0, unsigned b1)
{
    asm volatile(
        "mma.sync.aligned.m16n8k16.row.col.f32.f16.f16.f32 "
        "{%0,%1,%2,%3}, {%4,%5,%6,%7}, {%8,%9}, {%0,%1,%2,%3};"
        : "+f"(c0), "+f"(c1), "+f"(c2), "+f"(c3)
        : "r"(a0), "r"(a1), "r"(a2), "r"(a3), "r"(b0), "r"(b1));
}

__device__ __forceinline__ void ldsm_x4(
    unsigned& r0, unsigned& r1, unsigned& r2, unsigned& r3, uint32_t addr)
{
    asm volatile("ldmatrix.sync.aligned.m8n8.x4.shared.b16 {%0,%1,%2,%3}, [%4];"
                 : "=r"(r0), "=r"(r1), "=r"(r2), "=r"(r3) : "r"(addr));
}

__device__ __forceinline__ void ldsm_x4t(
    unsigned& r0, unsigned& r1, unsigned& r2, unsigned& r3, uint32_t addr)
{
    asm volatile("ldmatrix.sync.aligned.m8n8.x4.trans.shared.b16 {%0,%1,%2,%3}, [%4];"
                 : "=r"(r0), "=r"(r1), "=r"(r2), "=r"(r3) : "r"(addr));
}

// ---------------------------------------------------------------------------
// Kernel 1: N-split tensor-core GEMM. Each CTA: 128 rows x 64 cols (one head
// pair). grid = 2*ceil(NN/128); bx&1 selects the N-half. 3 CTAs/SM target.
// Fused attention dots (heads are 32-wide -> CTA-local) + packed fp16 h.
// ---------------------------------------------------------------------------
#define XP 72      // x tile pitch (halves): 36 words/row -> 4-bank rotation
#define WP 72      // W tile pitch (halves)
#define HP 66      // h staging pitch (halves): odd-word rotation

__global__ void __launch_bounds__(256, 3) k_gemm(
    const float* __restrict__ x, const float* __restrict__ W,
    const float* __restrict__ att_src, const float* __restrict__ att_dst)
{
    __shared__ __align__(16) __half xs[128 * XP];   // [r][k] 18.4 KB (reused for h)
    __shared__ __align__(16) __half wk[64 * WP];    // [k][n] 9.2 KB
    __shared__ float asmem[64], admem[64];

    const int t = threadIdx.x;
    const int bx = blockIdx.x;
    const int tile = bx >> 1;
    const int nhalf = bx & 1;
    const int C0 = nhalf * 64;
    const int w = t >> 5;
    const int lane = t & 31;
    const int quad = lane >> 2;
    const int tq = lane & 3;
    const int rw = 16 * w;

    // fold: zero degree counters (grid*256 >= NN)
    {
        int gidz = bx * 256 + t;
        if (gidz < NN) g_counts[gidz] = 0;
    }
    if (t < 64) { asmem[t] = att_src[C0 + t]; admem[t] = att_dst[C0 + t]; }

    const uint32_t xsBase = (uint32_t)__cvta_generic_to_shared(xs)
        + (uint32_t)(((rw + (lane & 15)) * XP + ((lane >> 4) << 3)) * 2);
    const uint32_t wkBase = (uint32_t)__cvta_generic_to_shared(wk)
        + (uint32_t)(((lane & 15) * WP + ((lane >> 4) << 3)) * 2);

    float acc[8][4];
#pragma unroll
    for (int nt = 0; nt < 8; nt++)
#pragma unroll
        for (int j = 0; j < 4; j++) acc[nt][j] = 0.0f;

    for (int kc = 0; kc < 2; kc++) {
        // --- stage x chunk: 128 rows x 64 k ---
#pragma unroll
        for (int i = 0; i < 8; i++) {
            int f = t + 256 * i;          // 2048 float4
            int r = f >> 4;
            int q = f & 15;
            int row = tile * 128 + r;
            if (row >= NN) row = NN - 1;
            float4 v = *reinterpret_cast<const float4*>(
                x + (size_t)row * INC + kc * 64 + q * 4);
            __half2 h01 = __floats2half2_rn(v.x, v.y);
            __half2 h23 = __floats2half2_rn(v.z, v.w);
            uint2 pk = make_uint2(*reinterpret_cast<unsigned*>(&h01),
                                  *reinterpret_cast<unsigned*>(&h23));
            *reinterpret_cast<uint2*>(&xs[r * XP + q * 4]) = pk;
        }
        // --- stage W chunk: 64 k-rows x 64 n (this CTA's half) ---
#pragma unroll
        for (int i = 0; i < 4; i++) {
            int f = t + 256 * i;          // 1024 float4
            int kk = f >> 4;              // 16 float4 per k-row
            int q = f & 15;
            float4 v = *reinterpret_cast<const float4*>(
                W + (size_t)(kc * 64 + kk) * HC + C0 + q * 4);
            __half2 h01 = __floats2half2_rn(v.x, v.y);
            __half2 h23 = __floats2half2_rn(v.z, v.w);
            uint2 pk = make_uint2(*reinterpret_cast<unsigned*>(&h01),
                                  *reinterpret_cast<unsigned*>(&h23));
            *reinterpret_cast<uint2*>(&wk[kk * WP + q * 4]) = pk;
        }
        __syncthreads();

#pragma unroll
        for (int ks = 0; ks < 4; ks++) {
            unsigned a0, a1, a2, a3;
            ldsm_x4(a0, a1, a2, a3, xsBase + ks * 32);
            const uint32_t bks = wkBase + (uint32_t)(ks * 16 * WP * 2);
#pragma unroll
            for (int nt2 = 0; nt2 < 4; nt2++) {
                unsigned b0, b1, b2, b3;
                ldsm_x4t(b0, b1, b2, b3, bks + nt2 * 32);
                mma16816(acc[2 * nt2][0], acc[2 * nt2][1],
                         acc[2 * nt2][2], acc[2 * nt2][3],
                         a0, a1, a2, a3, b0, b1);
                mma16816(acc[2 * nt2 + 1][0], acc[2 * nt2 + 1][1],
                         acc[2 * nt2 + 1][2], acc[2 * nt2 + 1][3],
                         a0, a1, a2, a3, b2, b3);
            }
        }
        __syncthreads();
    }

    // --- fused attention dots for this CTA's 2 heads ---
    float ps0[2] = {0, 0}, pd0[2] = {0, 0};
    float ps1[2] = {0, 0}, pd1[2] = {0, 0};
#pragma unroll
    for (int nt = 0; nt < 8; nt++) {
        const int hl = nt >> 2;               // local head 0/1
        const int cl = nt * 8 + tq * 2;       // local col
        const float As0 = asmem[cl], As1 = asmem[cl + 1];
        const float Ad0 = admem[cl], Ad1 = admem[cl + 1];
        ps0[hl] += acc[nt][0] * As0 + acc[nt][1] * As1;
        pd0[hl] += acc[nt][0] * Ad0 + acc[nt][1] * Ad1;
        ps1[hl] += acc[nt][2] * As0 + acc[nt][3] * As1;
        pd1[hl] += acc[nt][2] * Ad0 + acc[nt][3] * Ad1;
    }
#pragma unroll
    for (int o = 1; o <= 2; o <<= 1) {
#pragma unroll
        for (int hl = 0; hl < 2; hl++) {
            ps0[hl] += __shfl_xor_sync(0xffffffffu, ps0[hl], o);
            pd0[hl] += __shfl_xor_sync(0xffffffffu, pd0[hl], o);
            ps1[hl] += __shfl_xor_sync(0xffffffffu, ps1[hl], o);
            pd1[hl] += __shfl_xor_sync(0xffffffffu, pd1[hl], o);
        }
    }
    const int r0 = tile * 128 + rw + quad;
    const int r1 = r0 + 8;
    if (tq == 0) {
        if (r0 < NN) {
#pragma unroll
            for (int hl = 0; hl < 2; hl++) {
                g_asrc[r0 * 4 + nhalf * 2 + hl] = ps0[hl];
                g_adst[r0 * 4 + nhalf * 2 + hl] = pd0[hl];
            }
        }
        if (r1 < NN) {
#pragma unroll
            for (int hl = 0; hl < 2; hl++) {
                g_asrc[r1 * 4 + nhalf * 2 + hl] = ps1[hl];
                g_adst[r1 * 4 + nhalf * 2 + hl] = pd1[hl];
            }
        }
    }

    // --- stage h half into smem: local packed [r][m*2 + hl], pitch HP ---
    __half* hs = xs;   // 128 * 66 halves = 16.9 KB <= xs
    const int lr0 = rw + quad;
#pragma unroll
    for (int nt = 0; nt < 8; nt++) {
        const int cl = nt * 8 + tq * 2;
        const int p0 = (cl & 31) * 2 + (cl >> 5);
        const int p1 = ((cl + 1) & 31) * 2 + ((cl + 1) >> 5);
        hs[lr0 * HP + p0] = __float2half_rn(acc[nt][0]);
        hs[lr0 * HP + p1] = __float2half_rn(acc[nt][1]);
        hs[(lr0 + 8) * HP + p0] = __float2half_rn(acc[nt][2]);
        hs[(lr0 + 8) * HP + p1] = __float2half_rn(acc[nt][3]);
    }
    __syncthreads();

    // --- copy out: per (row, m) one uint (heads nhalf*2, nhalf*2+1) ---
    unsigned* gout = reinterpret_cast<unsigned*>(g_hp);
#pragma unroll
    for (int i = 0; i < 16; i++) {
        int f = t + 256 * i;          // 4096 uints
        int lr = f >> 5;
        int m = f & 31;
        int row = tile * 128 + lr;
        if (row < NN) {
            unsigned v = *reinterpret_cast<const unsigned*>(&hs[lr * HP + m * 2]);
            gout[(size_t)row * 64 + m * 2 + nhalf] = v;
        }
    }
}

// ---------------------------------------------------------------------------
// Kernel 2: fused histogram + numerator exp + AOS record write.
// ---------------------------------------------------------------------------
__global__ void k_scatter(const int* __restrict__ ei, int E) {
    int e = blockIdx.x * blockDim.x + threadIdx.x;
    if (e >= E) return;
    int src = ei[e];
    int dst = ei[E + e];
    int epos = atomicAdd(&g_counts[dst], 1);
    if (epos >= SLOT) return;   // astronomically unlikely; drop to stay safe
    const float4 as = *reinterpret_cast<const float4*>(g_asrc + (size_t)src * 4);
    const float4 ad = *reinterpret_cast<const float4*>(g_adst + (size_t)dst * 4);
    float p0 = __expf(lrelu(as.x + ad.x)) * PSCALE;
    float p1 = __expf(lrelu(as.y + ad.y)) * PSCALE;
    float p2 = __expf(lrelu(as.z + ad.z)) * PSCALE;
    float p3 = __expf(lrelu(as.w + ad.w)) * PSCALE;
    __half2 h01 = __floats2half2_rn(p0, p1);
    __half2 h23 = __floats2half2_rn(p2, p3);
    int4 rec;
    rec.x = src;
    rec.y = *reinterpret_cast<int*>(&h01);
    rec.z = *reinterpret_cast<int*>(&h23);
    rec.w = 0;
    g_edge[(size_t)dst * SLOT + epos] = rec;
}

// ---------------------------------------------------------------------------
// Kernel 3: warp-per-dst aggregate (measured-good R6/R8 form).
// ---------------------------------------------------------------------------
__global__ void __launch_bounds__(256) k_agg(float* __restrict__ out,
                                             const float* __restrict__ bias) {
    const int gid = blockIdx.x * blockDim.x + threadIdx.x;
    const int node = gid >> 5;
    const int lane = gid & 31;
    if (node >= NN) return;

    const uint2* hp = reinterpret_cast<const uint2*>(g_hp);

    const float4 as = *reinterpret_cast<const float4*>(g_asrc + (size_t)node * 4);
    const float4 ad = *reinterpret_cast<const float4*>(g_adst + (size_t)node * 4);
    float p0 = __expf(lrelu(as.x + ad.x)) * PSCALE;
    float p1 = __expf(lrelu(as.y + ad.y)) * PSCALE;
    float p2 = __expf(lrelu(as.z + ad.z)) * PSCALE;
    float p3 = __expf(lrelu(as.w + ad.w)) * PSCALE;
    uint2 hv = hp[(size_t)node * 32 + lane];
    float2 f01 = __half22float2(*reinterpret_cast<__half2*>(&hv.x));
    float2 f23 = __half22float2(*reinterpret_cast<__half2*>(&hv.y));
    float A0 = p0 * f01.x, A1 = p1 * f01.y;
    float A2 = p2 * f23.x, A3 = p3 * f23.y;
    float D0 = p0, D1 = p1, D2 = p2, D3 = p3;

    const int4* ge = g_edge + (size_t)node * SLOT;
    int deg = g_counts[node];
    if (deg > SLOT) deg = SLOT;
    const __half2 z2 = __float2half2_rn(0.0f);

#define EDGEH(rec, hh)                                                        \
    {                                                                         \
        __half2 pp01 = *reinterpret_cast<const __half2*>(&(rec).y);           \
        __half2 pp23 = *reinterpret_cast<const __half2*>(&(rec).z);           \
        __half2 gg01 = *reinterpret_cast<const __half2*>(&(hh).x);            \
        __half2 gg23 = *reinterpret_cast<const __half2*>(&(hh).y);            \
        acc01 = __hfma2(pp01, gg01, acc01);                                   \
        acc23 = __hfma2(pp23, gg23, acc23);                                   \
        den01 = __hadd2(den01, pp01);                                         \
        den23 = __hadd2(den23, pp23);                                         \
    }
#define FLUSH                                                                 \
    {                                                                         \
        float2 t;                                                             \
        t = __half22float2(acc01); A0 += t.x; A1 += t.y;                      \
        t = __half22float2(acc23); A2 += t.x; A3 += t.y;                      \
        t = __half22float2(den01); D0 += t.x; D1 += t.y;                      \
        t = __half22float2(den23); D2 += t.x; D3 += t.y;                      \
        acc01 = z2; acc23 = z2; den01 = z2; den23 = z2;                       \
    }

    int j = 0;
    for (; j + 8 <= deg; j += 8) {
        int4 e0 = ge[j],     e1 = ge[j + 1], e2 = ge[j + 2], e3 = ge[j + 3];
        int4 e4 = ge[j + 4], e5 = ge[j + 5], e6 = ge[j + 6], e7 = ge[j + 7];
        uint2 h0 = hp[(size_t)e0.x * 32 + lane];
        uint2 h1 = hp[(size_t)e1.x * 32 + lane];
        uint2 h2 = hp[(size_t)e2.x * 32 + lane];
        uint2 h3 = hp[(size_t)e3.x * 32 + lane];
        uint2 h4 = hp[(size_t)e4.x * 32 + lane];
        uint2 h5 = hp[(size_t)e5.x * 32 + lane];
        uint2 h6 = hp[(size_t)e6.x * 32 + lane];
        uint2 h7 = hp[(size_t)e7.x * 32 + lane];
        __half2 acc01 = z2, acc23 = z2, den01 = z2, den23 = z2;
        EDGEH(e0, h0) EDGEH(e1, h1) EDGEH(e2, h2) EDGEH(e3, h3)
        FLUSH
        EDGEH(e4, h4) EDGEH(e5, h5) EDGEH(e6, h6) EDGEH(e7, h7)
        FLUSH
    }
    for (; j + 4 <= deg; j += 4) {
        int4 e0 = ge[j], e1 = ge[j + 1], e2 = ge[j + 2], e3 = ge[j + 3];
        uint2 h0 = hp[(size_t)e0.x * 32 + lane];
        uint2 h1 = hp[(size_t)e1.x * 32 + lane];
        uint2 h2 = hp[(size_t)e2.x * 32 + lane];
        uint2 h3 = hp[(size_t)e3.x * 32 + lane];
        __half2 acc01 = z2, acc23 = z2, den01 = z2, den23 = z2;
        EDGEH(e0, h0) EDGEH(e1, h1) EDGEH(e2, h2) EDGEH(e3, h3)
        FLUSH
    }
    {
        __half2 acc01 = z2, acc23 = z2, den01 = z2, den23 = z2;
        for (; j < deg; j++) {
            int4 e0 = ge[j];
            uint2 h0 = hp[(size_t)e0.x * 32 + lane];
            EDGEH(e0, h0)
        }
        FLUSH
    }
#undef EDGEH
#undef FLUSH

    float v = 0.25f * (A0 / (D0 + 1e-16f) + A1 / (D1 + 1e-16f)
                     + A2 / (D2 + 1e-16f) + A3 / (D3 + 1e-16f))
            + bias[lane];
    out[(size_t)node * 32 + lane] = v > 0.0f ? v : 0.0f;
}

// ---------------------------------------------------------------------------
extern "C" void kernel_launch(void* const* d_in, const int* in_sizes, int n_in,
                              void* d_out, int out_size) {
    const float* x       = (const float*)d_in[0];
    const int*   ei      = (const int*)  d_in[1];
    const float* W       = (const float*)d_in[2];
    const float* att_src = (const float*)d_in[3];
    const float* att_dst = (const float*)d_in[4];
    const float* bias    = (const float*)d_in[5];
    float*       out     = (float*)d_out;

    const int E = in_sizes[1] / 2;

    k_gemm<<<2 * ((NN + 127) / 128), 256>>>(x, W, att_src, att_dst);
    k_scatter<<<(E + 255) / 256, 256>>>(ei, E);
    k_agg<<<(NN * 32 + 255) / 256, 256>>>(out, bias);
}